// round 13
// baseline (speedup 1.0000x reference)
#include <cuda_runtime.h>
#include <cuda_fp16.h>
#include <stdint.h>

#define N_NODES 100000
#define BATCH   50000
#define K       10
#define DIM     128

// Packed fp16 table, 25.6 MB (L2-resident hot set).
__device__ __half g_tab16[N_NODES * DIM];

// ---------------------------------------------------------------------------
// Pass 1: fp32 -> fp16. One thread = 32B of table (4 LDG.128 + 2 STG.128).
// ---------------------------------------------------------------------------
__global__ __launch_bounds__(256) void convert_kernel(const float4* __restrict__ feat)
{
    const int i = blockIdx.x * blockDim.x + threadIdx.x;
    const int n32 = N_NODES * DIM / 16;                 // 800k
    if (i >= n32) return;

    float4 a = __ldg(&feat[i * 4 + 0]);
    float4 b = __ldg(&feat[i * 4 + 1]);
    float4 c = __ldg(&feat[i * 4 + 2]);
    float4 d = __ldg(&feat[i * 4 + 3]);

    __half2 h0 = __float22half2_rn(make_float2(a.x, a.y));
    __half2 h1 = __float22half2_rn(make_float2(a.z, a.w));
    __half2 h2 = __float22half2_rn(make_float2(b.x, b.y));
    __half2 h3 = __float22half2_rn(make_float2(b.z, b.w));
    __half2 h4 = __float22half2_rn(make_float2(c.x, c.y));
    __half2 h5 = __float22half2_rn(make_float2(c.z, c.w));
    __half2 h6 = __float22half2_rn(make_float2(d.x, d.y));
    __half2 h7 = __float22half2_rn(make_float2(d.z, d.w));

    uint4 p0, p1;
    p0.x = *reinterpret_cast<unsigned*>(&h0);
    p0.y = *reinterpret_cast<unsigned*>(&h1);
    p0.z = *reinterpret_cast<unsigned*>(&h2);
    p0.w = *reinterpret_cast<unsigned*>(&h3);
    p1.x = *reinterpret_cast<unsigned*>(&h4);
    p1.y = *reinterpret_cast<unsigned*>(&h5);
    p1.z = *reinterpret_cast<unsigned*>(&h6);
    p1.w = *reinterpret_cast<unsigned*>(&h7);

    uint4* dst = reinterpret_cast<uint4*>(g_tab16);
    dst[i * 2 + 0] = p0;
    dst[i * 2 + 1] = p1;
}

static __device__ __forceinline__ __half2 H2(const unsigned& u)
{
    return *reinterpret_cast<const __half2*>(&u);
}

// ---------------------------------------------------------------------------
// Pass 2: gather-mean with SINGLE-LINE warp requests.
// One warp per row. Each lane loads 4B (one half2): lane i reads word i of
// the row's lo 128B line, and word i of the hi 128B line. Every warp load
// instruction therefore touches EXACTLY ONE 128B cache line (4 sectors,
// 1 L1TEX wavefront, no multi-line split) — the only request shape not yet
// tried against the 15.8us fp16 wall. 22 single-line requests per row.
// ---------------------------------------------------------------------------
__global__ __launch_bounds__(256) void gather_kernel(
    const int* __restrict__ nodes,
    const int* __restrict__ neighbours,
    float2* __restrict__ out)
{
    const int warp = (blockIdx.x * blockDim.x + threadIdx.x) >> 5;
    const int lane = threadIdx.x & 31;
    if (warp >= BATCH) return;

    int idx[K + 1];
    idx[0] = __ldg(&nodes[warp]);
#pragma unroll
    for (int k = 0; k < K; k++) idx[k + 1] = __ldg(&neighbours[warp * K + k]);

    const unsigned* __restrict__ tab = reinterpret_cast<const unsigned*>(g_tab16);
    // fp16 row = 256B = 64 words; lo line words [0,32), hi line words [32,64).

    unsigned vlo[K + 1], vhi[K + 1];
#pragma unroll
    for (int k = 0; k < K + 1; k++) {
        const unsigned* base = tab + idx[k] * 64;
        vlo[k] = __ldg(base + lane);          // one 128B line per warp request
        vhi[k] = __ldg(base + 32 + lane);     // one 128B line per warp request
    }

    __half2 alo = H2(vlo[0]);
    __half2 ahi = H2(vhi[0]);
#pragma unroll
    for (int k = 1; k < K + 1; k++) {
        alo = __hadd2(alo, H2(vlo[k]));
        ahi = __hadd2(ahi, H2(vhi[k]));
    }

    const float s = 1.0f / (float)(K + 1);
    float2 flo = __half22float2(alo);
    float2 fhi = __half22float2(ahi);

    flo.x *= s; flo.y *= s;
    fhi.x *= s; fhi.y *= s;

    // Output row = 128 floats = 64 float2. Lane owns cols {2*lane, 2*lane+1}
    // (lo) and {64+2*lane, 65+2*lane} (hi): two coalesced 256B warp stores.
    float2* orow = out + (size_t)warp * 64;
    __stcs(&orow[lane], flo);
    __stcs(&orow[32 + lane], fhi);
}

extern "C" void kernel_launch(void* const* d_in, const int* in_sizes, int n_in,
                              void* d_out, int out_size)
{
    const int*    nodes      = (const int*)d_in[0];
    const int*    neighbours = (const int*)d_in[1];
    const float4* features   = (const float4*)d_in[2];
    float2*       out        = (float2*)d_out;

    const int n32 = N_NODES * DIM / 16;
    convert_kernel<<<(n32 + 255) / 256, 256>>>(features);

    const int warps_per_block = 256 / 32;
    const int blocks = (BATCH + warps_per_block - 1) / warps_per_block;
    gather_kernel<<<blocks, 256>>>(nodes, neighbours, out);
}

// round 14
// speedup vs baseline: 1.4484x; 1.4484x over previous
#include <cuda_runtime.h>

#define BATCH 50000
#define K 10
#define DIM 128
#define VECS_PER_ROW (DIM / 4)   // 32 float4 per row — one per lane

// FINAL: fp32 one-pass gather-mean, pinned at the B300 LTS sector cap.
// 550k gathered 512B rows + 25.6MB output = 307MB of L2 traffic; at the
// ~6300 B/cyc chip LTS ceiling this is ~21.2us — measured invariant across
// occupancy (48-85%), MLP staging, cp.async, and every fp16 byte-reduction
// attempt (all of which hit a separate ~10.5TB/s wall plus a ~9us convert
// tax). One warp per output row; each lane owns one float4 (32 x 16B).
__global__ __launch_bounds__(256) void mean_agg_kernel(
    const int* __restrict__ nodes,        // [BATCH]
    const int* __restrict__ neighbours,   // [BATCH, K]
    const float4* __restrict__ features,  // [N_NODES, 32] as float4
    float4* __restrict__ out)             // [BATCH, 32] as float4
{
    const int warp = (blockIdx.x * blockDim.x + threadIdx.x) >> 5;
    const int lane = threadIdx.x & 31;
    if (warp >= BATCH) return;

    // 11 row ids (self + K neighbours); uniform across the warp -> broadcast.
    int idx[K + 1];
    idx[0] = __ldg(&nodes[warp]);
#pragma unroll
    for (int k = 0; k < K; k++) idx[k + 1] = __ldg(&neighbours[warp * K + k]);

    // 11 gathered float4 loads; each warp request = 4 x 128B lines, the
    // request shape that reaches the LTS sector cap.
    float4 v[K + 1];
#pragma unroll
    for (int k = 0; k < K + 1; k++) {
        v[k] = __ldg(&features[(long long)idx[k] * VECS_PER_ROW + lane]);
    }

    float4 acc = v[0];
#pragma unroll
    for (int k = 1; k < K + 1; k++) {
        acc.x += v[k].x;
        acc.y += v[k].y;
        acc.z += v[k].z;
        acc.w += v[k].w;
    }

    const float s = 1.0f / (float)(K + 1);
    acc.x *= s; acc.y *= s; acc.z *= s; acc.w *= s;

    // Write-once output: stream past L2 so it doesn't evict the features.
    __stcs(&out[(long long)warp * VECS_PER_ROW + lane], acc);
}

extern "C" void kernel_launch(void* const* d_in, const int* in_sizes, int n_in,
                              void* d_out, int out_size)
{
    const int*    nodes      = (const int*)d_in[0];
    const int*    neighbours = (const int*)d_in[1];
    const float4* features   = (const float4*)d_in[2];
    float4*       out        = (float4*)d_out;

    // One warp per row, 8 warps per 256-thread block.
    const int warps_per_block = 256 / 32;
    const int blocks = (BATCH + warps_per_block - 1) / warps_per_block;
    mean_agg_kernel<<<blocks, 256>>>(nodes, neighbours, features, out);
}